// round 16
// baseline (speedup 1.0000x reference)
#include <cuda_runtime.h>
#include <cuda_fp16.h>
#include <math.h>
#include <stdint.h>

#define Bc   4
#define Sc   1024
#define Dc   1024
#define Hc   16
#define DKc  64
#define Mc   (Bc*Sc)        // 4096
#define BHc  (Bc*Hc)        // 64
#define YSIZE (Bc*Sc*Dc)

// ---------------- device scratch ----------------
__device__ __half g_Q[Mc*Dc];       // [bh][s][dk] fp16
__device__ __half g_K[Mc*Dc];       // [bh][s][dk] fp16
__device__ __half g_VT[Mc*Dc];      // [bh][dk][s] fp16
__device__ __half g_att[Mc*Dc];     // [m][h*dk]  fp16
__device__ float g_fc[Mc*Dc];       // fc + resid (fp32)
__device__ __half g_WT[4][Dc*Dc];   // WT[n][k] fp16
__device__ float g_psum[BHc*8*Sc];  // [bh][nt][q] partial row sums
__device__ __half g_pexp[(size_t)BHc*Sc*Sc];  // unnormalized exp(x), fp16

// ---------------- helpers ----------------
__device__ __forceinline__ uint32_t smem_u32(const void* p) {
    uint32_t a;
    asm("{ .reg .u64 t; cvta.to.shared.u64 t, %1; cvt.u32.u64 %0, t; }" : "=r"(a) : "l"(p));
    return a;
}
__device__ __forceinline__ uint32_t packh2(float x, float y) {
    __half2 h = __float22half2_rn(make_float2(x, y));
    return *(uint32_t*)&h;
}
__device__ __forceinline__ void ldsm4(uint32_t* r, uint32_t addr) {
    asm volatile("ldmatrix.sync.aligned.m8n8.x4.shared.b16 {%0,%1,%2,%3}, [%4];"
        : "=r"(r[0]), "=r"(r[1]), "=r"(r[2]), "=r"(r[3]) : "r"(addr));
}
__device__ __forceinline__ void mma_f16(float* c, const uint32_t* a, const uint32_t* b) {
    asm volatile("mma.sync.aligned.m16n8k16.row.col.f32.f16.f16.f32 "
        "{%0,%1,%2,%3}, {%4,%5,%6,%7}, {%8,%9}, {%0,%1,%2,%3};"
        : "+f"(c[0]), "+f"(c[1]), "+f"(c[2]), "+f"(c[3])
        : "r"(a[0]), "r"(a[1]), "r"(a[2]), "r"(a[3]), "r"(b[0]), "r"(b[1]));
}
__device__ __forceinline__ void cpa16(uint32_t dst, const void* src) {
    asm volatile("cp.async.cg.shared.global [%0], [%1], 16;" :: "r"(dst), "l"(src));
}
#define CP_COMMIT() asm volatile("cp.async.commit_group;" ::: "memory")
__device__ __forceinline__ void cp_wait0() { asm volatile("cp.async.wait_group 0;" ::: "memory"); }
__device__ __forceinline__ void cp_wait1() { asm volatile("cp.async.wait_group 1;" ::: "memory"); }
__device__ __forceinline__ void cp_wait2() { asm volatile("cp.async.wait_group 2;" ::: "memory"); }
__device__ __forceinline__ void cp_wait(int n) {
    if (n == 0) cp_wait0(); else cp_wait1();
}
__device__ __forceinline__ void stcs4(float* p, float4 v) {
    asm volatile("st.global.cs.v4.f32 [%0], {%1,%2,%3,%4};"
        :: "l"(p), "f"(v.x), "f"(v.y), "f"(v.z), "f"(v.w) : "memory");
}
__device__ __forceinline__ void stcs2u(__half* p, uint2 v) {
    asm volatile("st.global.cs.v2.u32 [%0], {%1,%2};"
        :: "l"(p), "r"(v.x), "r"(v.y) : "memory");
}

// ---------------- weight transpose: W[k][n] -> WT[n][k] fp16 ----------------
__global__ void transpose_w(const float* __restrict__ W0, const float* __restrict__ W1,
                            const float* __restrict__ W2, const float* __restrict__ W3)
{
    __shared__ float t[32][33];
    const float* W = (blockIdx.z == 0) ? W0 : (blockIdx.z == 1) ? W1 : (blockIdx.z == 2) ? W2 : W3;
    __half* o = g_WT[blockIdx.z];
    const int k0 = blockIdx.y * 32, n0 = blockIdx.x * 32;
    const int tx = threadIdx.x, ty = threadIdx.y;   // 32 x 8
#pragma unroll
    for (int i = 0; i < 32; i += 8)
        t[ty + i][tx] = W[(size_t)(k0 + ty + i) * Dc + n0 + tx];
    __syncthreads();
#pragma unroll
    for (int i = 0; i < 32; i += 8)
        o[(size_t)(n0 + ty + i) * Dc + k0 + tx] = __float2half(t[tx][ty + i]);
}

// ===========================================================================
// fp16 GEMM, 3-stage cp.async pipeline, ONE barrier per k-tile (as R14).
// ===========================================================================
#define GRS 80
#define GTILE 10240
#define GBUF  (2*GTILE)
#define SM_G  (128*132*4)
#define STG 132

__global__ __launch_bounds__(256, 2) void mma_gemm(const float* __restrict__ A0,
                                                   const float* __restrict__ A1,
                                                   const float* __restrict__ A2,
                                                   int modeParam,
                                                   const float* __restrict__ bias,
                                                   const float* __restrict__ resid)
{
    extern __shared__ __align__(16) char smem[];
    const uint32_t sb = smem_u32(smem);
    const int tid  = threadIdx.x;
    const int lane = tid & 31;
    const int wid  = tid >> 5;
    const int wm   = wid >> 2;
    const int wn   = wid & 3;
    const int m0 = blockIdx.y * 128;
    const int n0 = blockIdx.x * 128;

    const int mode = (modeParam >= 0) ? modeParam : (int)blockIdx.z;
    const bool a16 = (mode == 3);
    const float* Af = (mode == 0) ? A0 : (mode == 1) ? A1 : A2;
    const __half* B = g_WT[mode];

    const int fr3 = tid >> 3, fc3 = (tid & 7) * 4;
    const int ra0 = tid >> 2,          ca0 = (tid & 3) * 8;
    const int ra1 = (tid + 256) >> 2,  ca1 = ((tid + 256) & 3) * 8;
    const uint32_t sA0 = ra0 * GRS + ca0 * 2;
    const uint32_t sA1 = ra1 * GRS + ca1 * 2;

    const int arow = lane & 15;
    const int acol = (lane & 16) ? 8 : 0;
    const int brow = ((lane & 16) >> 1) + (lane & 7);
    const int bcol = (lane & 8);

    float acc[4][4][4];
#pragma unroll
    for (int i = 0; i < 4; i++)
#pragma unroll
        for (int j = 0; j < 4; j++)
#pragma unroll
            for (int q = 0; q < 4; q++) acc[i][j][q] = 0.0f;

    float4 pa[4];
    {
        cpa16(sb + GTILE + sA0, B + (size_t)(n0 + ra0) * 1024 + ca0);
        cpa16(sb + GTILE + sA1, B + (size_t)(n0 + ra1) * 1024 + ca1);
        if (a16) {
            cpa16(sb + sA0, g_att + (size_t)(m0 + ra0) * 1024 + ca0);
            cpa16(sb + sA1, g_att + (size_t)(m0 + ra1) * 1024 + ca1);
        }
        CP_COMMIT();
        cpa16(sb + GBUF + GTILE + sA0, B + (size_t)(n0 + ra0) * 1024 + 32 + ca0);
        cpa16(sb + GBUF + GTILE + sA1, B + (size_t)(n0 + ra1) * 1024 + 32 + ca1);
        if (a16) {
            cpa16(sb + GBUF + sA0, g_att + (size_t)(m0 + ra0) * 1024 + 32 + ca0);
            cpa16(sb + GBUF + sA1, g_att + (size_t)(m0 + ra1) * 1024 + 32 + ca1);
        }
        CP_COMMIT();
    }
    if (!a16) {
#pragma unroll
        for (int j = 0; j < 4; j++)
            pa[j] = *(const float4*)(Af + (size_t)(m0 + fr3 + 32 * j) * 1024 + fc3);
        char* As = smem;
#pragma unroll
        for (int j = 0; j < 4; j++) {
            uint2 h = make_uint2(packh2(pa[j].x, pa[j].y), packh2(pa[j].z, pa[j].w));
            *(uint2*)(As + (fr3 + 32 * j) * GRS + fc3 * 2) = h;
        }
#pragma unroll
        for (int j = 0; j < 4; j++)
            pa[j] = *(const float4*)(Af + (size_t)(m0 + fr3 + 32 * j) * 1024 + 32 + fc3);
    }

    for (int kt = 0; kt < 32; kt++) {
        cp_wait(kt == 31 ? 0 : 1);
        __syncthreads();
        if (kt + 2 <= 31) {
            const int ko = (kt + 2) * 32;
            const uint32_t bb = sb + ((kt + 2) % 3) * GBUF;
            cpa16(bb + GTILE + sA0, B + (size_t)(n0 + ra0) * 1024 + ko + ca0);
            cpa16(bb + GTILE + sA1, B + (size_t)(n0 + ra1) * 1024 + ko + ca1);
            if (a16) {
                cpa16(bb + sA0, g_att + (size_t)(m0 + ra0) * 1024 + ko + ca0);
                cpa16(bb + sA1, g_att + (size_t)(m0 + ra1) * 1024 + ko + ca1);
            }
            CP_COMMIT();
        }
        const uint32_t aB = sb + (kt % 3) * GBUF;
        const uint32_t bB = aB + GTILE;
#pragma unroll
        for (int ks = 0; ks < 2; ks++) {
            const int k0s = ks * 16;
            uint32_t af[4][4], bf[2][4];
#pragma unroll
            for (int mi = 0; mi < 4; mi++)
                ldsm4(af[mi], aB + (uint32_t)(wm*64 + mi*16 + arow) * GRS + (k0s + acol) * 2);
#pragma unroll
            for (int j = 0; j < 2; j++)
                ldsm4(bf[j], bB + (uint32_t)(wn*32 + j*16 + brow) * GRS + (k0s + bcol) * 2);
#pragma unroll
            for (int mi = 0; mi < 4; mi++)
#pragma unroll
                for (int ni = 0; ni < 4; ni++)
                    mma_f16(acc[mi][ni], af[mi], &bf[ni >> 1][(ni & 1) * 2]);
        }
        if (!a16) {
            if (kt + 1 <= 31) {
                char* As2 = smem + ((kt + 1) % 3) * GBUF;
#pragma unroll
                for (int j = 0; j < 4; j++) {
                    uint2 h = make_uint2(packh2(pa[j].x, pa[j].y), packh2(pa[j].z, pa[j].w));
                    *(uint2*)(As2 + (fr3 + 32 * j) * GRS + fc3 * 2) = h;
                }
            }
            if (kt + 2 <= 31) {
                const int ko = (kt + 2) * 32;
#pragma unroll
                for (int j = 0; j < 4; j++)
                    pa[j] = *(const float4*)(Af + (size_t)(m0 + fr3 + 32 * j) * 1024 + ko + fc3);
            }
        }
    }
    __syncthreads();

    float* stage = (float*)smem;
#pragma unroll
    for (int mi = 0; mi < 4; mi++)
#pragma unroll
        for (int ni = 0; ni < 4; ni++) {
            const int row = wm * 64 + mi * 16 + (lane >> 2);
            const int col = wn * 32 + ni * 8 + (lane & 3) * 2;
            *(float2*)&stage[row * STG + col]       = make_float2(acc[mi][ni][0], acc[mi][ni][1]);
            *(float2*)&stage[(row + 8) * STG + col] = make_float2(acc[mi][ni][2], acc[mi][ni][3]);
        }
    __syncthreads();

    if (mode <= 1) {
        __half* out = (mode == 0) ? g_Q : g_K;
#pragma unroll
        for (int i = 0; i < 16; i++) {
            const int e = tid + i * 256;
            const int r = e >> 5, c4 = (e & 31) * 4;
            float4 v = *(const float4*)&stage[r * STG + c4];
            const int m = m0 + r, b = m >> 10, s = m & 1023;
            const int n = n0 + c4, h = n >> 6, dk = n & 63;
            uint2 hv = make_uint2(packh2(v.x, v.y), packh2(v.z, v.w));
            *(uint2*)(out + (((size_t)(b * 16 + h) * 1024 + s) * 64 + dk)) = hv;
        }
    } else if (mode == 2) {
        const int r = tid & 127, half_ = tid >> 7;
        const int b = m0 >> 10, s0r = m0 & 1023;
#pragma unroll 8
        for (int j = 0; j < 64; j++) {
            const int c = half_ * 64 + j;
            const float v = stage[r * STG + c];
            const int n = n0 + c, hh = n >> 6, dk = n & 63;
            g_VT[((size_t)(b * 16 + hh) * 64 + dk) * 1024 + s0r + r] = __float2half(v);
        }
    } else {
#pragma unroll
        for (int i = 0; i < 16; i++) {
            const int e = tid + i * 256;
            const int r = e >> 5, c4 = (e & 31) * 4;
            float4 v = *(const float4*)&stage[r * STG + c4];
            const int m = m0 + r, n = n0 + c4;
            float4 bi = *(const float4*)(bias + n);
            float4 rs = *(const float4*)(resid + (size_t)m * 1024 + n);
            v.x += bi.x + rs.x; v.y += bi.y + rs.y;
            v.z += bi.z + rs.z; v.w += bi.w + rs.w;
            *(float4*)(g_fc + (size_t)m * 1024 + n) = v;
        }
    }
}

// ===========================================================================
// scores (fp16 mma, no-max softmax). pexp written with st.global.cs.
// ===========================================================================
#define SRS 144
#define SM_S (128*132*4)

__global__ __launch_bounds__(256, 2) void scores_mma(const float* __restrict__ rel,
                                                     const int*   __restrict__ mask)
{
    extern __shared__ __align__(16) char smem[];
    const uint32_t sb = smem_u32(smem);
    const uint32_t qB = sb, kB = sb + 128 * SRS;

    const int tid = threadIdx.x, lane = tid & 31, wid = tid >> 5;
    const int wm = wid >> 2, wn = wid & 3;
    const int bh = blockIdx.z, q0 = blockIdx.y * 128, n0 = blockIdx.x * 128;
    const size_t base = (size_t)bh * Sc * DKc;

    const int arow = lane & 15;
    const int acol = (lane & 16) ? 8 : 0;
    const int brow = ((lane & 16) >> 1) + (lane & 7);
    const int bcol = (lane & 8);

    {
#pragma unroll
        for (int i = 0; i < 4; i++) {
            const int e = tid + i * 256;
            const int r = e >> 3, c16 = (e & 7) * 8;
            cpa16(qB + (uint32_t)r * SRS + c16 * 2, g_Q + base + (size_t)(q0 + r) * 64 + c16);
            cpa16(kB + (uint32_t)r * SRS + c16 * 2, g_K + base + (size_t)(n0 + r) * 64 + c16);
        }
        CP_COMMIT();
        cp_wait0();
    }
    __syncthreads();

    float acc[4][4][4];
#pragma unroll
    for (int i = 0; i < 4; i++)
#pragma unroll
        for (int j = 0; j < 4; j++)
#pragma unroll
            for (int q = 0; q < 4; q++) acc[i][j][q] = 0.0f;

#pragma unroll
    for (int ks = 0; ks < 4; ks++) {
        const int k0s = ks * 16;
        uint32_t af[4][4], bf[2][4];
#pragma unroll
        for (int mi = 0; mi < 4; mi++)
            ldsm4(af[mi], qB + (uint32_t)(wm*64 + mi*16 + arow) * SRS + (k0s + acol) * 2);
#pragma unroll
        for (int j = 0; j < 2; j++)
            ldsm4(bf[j], kB + (uint32_t)(wn*32 + j*16 + brow) * SRS + (k0s + bcol) * 2);
#pragma unroll
        for (int mi = 0; mi < 4; mi++)
#pragma unroll
            for (int ni = 0; ni < 4; ni++)
                mma_f16(acc[mi][ni], af[mi], &bf[ni >> 1][(ni & 1) * 2]);
    }
    __syncthreads();

    float* stage = (float*)smem;
#pragma unroll
    for (int mi = 0; mi < 4; mi++)
#pragma unroll
        for (int ni = 0; ni < 4; ni++) {
            const int row = wm * 64 + mi * 16 + (lane >> 2);
            const int col = wn * 32 + ni * 8 + (lane & 3) * 2;
            *(float2*)&stage[row * STG + col]       = make_float2(acc[mi][ni][0], acc[mi][ni][1]);
            *(float2*)&stage[(row + 8) * STG + col] = make_float2(acc[mi][ni][2], acc[mi][ni][3]);
        }
    __syncthreads();

    const int b = bh >> 4;
#pragma unroll
    for (int i = 0; i < 16; i++) {
        const int r = i * 8 + wid;
        const int q = q0 + r;
        const int n = n0 + lane * 4;
        float4 v = *(const float4*)&stage[r * STG + lane * 4];
        const size_t ridx = ((size_t)b * Sc + q) * Sc + n;
        float4 r4 = *(const float4*)(rel + ridx);
        int4   m4 = *(const int4*)(mask + ridx);
        float4 e;
        e.x = m4.x ? 0.0f : __expf(fmaf(v.x, 0.125f, r4.x));
        e.y = m4.y ? 0.0f : __expf(fmaf(v.y, 0.125f, r4.y));
        e.z = m4.z ? 0.0f : __expf(fmaf(v.z, 0.125f, r4.z));
        e.w = m4.w ? 0.0f : __expf(fmaf(v.w, 0.125f, r4.w));
        float s = e.x + e.y + e.z + e.w;
#pragma unroll
        for (int o = 16; o > 0; o >>= 1) s += __shfl_xor_sync(0xffffffffu, s, o);
        uint2 hw = make_uint2(packh2(e.x, e.y), packh2(e.z, e.w));
        stcs2u(g_pexp + ((size_t)bh * Sc + q) * Sc + n, hw);
        if (lane == 0)
            g_psum[((size_t)bh * 8 + blockIdx.x) * Sc + q] = s;
    }
}

// ===========================================================================
// att (fp16 mma): grid (4,64), 2 q-units/CTA, k-tile 32, 4-STAGE pipeline,
// 1 barrier/tile; final p written with st.global.cs.
// ===========================================================================
#define AST 80
#define AT_PB (128*AST)             // 10240
#define AT_VB (64*AST)              // 5120
#define AT_BUF (AT_PB+AT_VB)        // 15360; 4 stages = 61440
#define AT_SINV 61440
#define SM_A (AT_SINV + 512)        // 61952
#define ATG 68

__global__ __launch_bounds__(256, 2) void att_mma(float* __restrict__ p)
{
    extern __shared__ __align__(16) char smem[];
    const uint32_t sb = smem_u32(smem);
    float* sinv = (float*)(smem + AT_SINV);   // [128]

    const int tid = threadIdx.x, lane = tid & 31, wid = tid >> 5;
    const int wm = wid >> 1, wn = wid & 1;
    const int bh = blockIdx.y;
    const __half* Vb = g_VT + (size_t)bh * 64 * 1024;

    const int ra0 = tid >> 2,          ca0 = (tid & 3) * 8;
    const int ra1 = (tid + 256) >> 2,  ca1 = ((tid + 256) & 3) * 8;
    const uint32_t sP0 = ra0 * AST + ca0 * 2;
    const uint32_t sP1 = ra1 * AST + ca1 * 2;
    const int rv = tid >> 2,           cv = (tid & 3) * 8;
    const uint32_t sV = rv * AST + cv * 2;
    const int r2 = tid >> 1, h16 = (tid & 1) * 16;

    const int arow = lane & 15;
    const int acol = (lane & 16) ? 8 : 0;
    const int brow = ((lane & 16) >> 1) + (lane & 7);
    const int bcol = (lane & 8);

    for (int qi = 0; qi < 2; qi++) {
        const int q0 = (blockIdx.x * 2 + qi) * 128;
        const __half* Pe = g_pexp + ((size_t)bh * 1024 + q0) * 1024;
        float* Pout = p + ((size_t)bh * 1024 + q0) * 1024;

        float acc[2][4][4];
#pragma unroll
        for (int i = 0; i < 2; i++)
#pragma unroll
            for (int j = 0; j < 4; j++)
#pragma unroll
                for (int q = 0; q < 4; q++) acc[i][j][q] = 0.0f;

        // prologue: tiles 0,1,2; sinv
#pragma unroll
        for (int s = 0; s < 3; s++) {
            const uint32_t bb = sb + s * AT_BUF;
            const int ko = s * 32;
            cpa16(bb + sP0,        Pe + (size_t)ra0 * 1024 + ko + ca0);
            cpa16(bb + sP1,        Pe + (size_t)ra1 * 1024 + ko + ca1);
            cpa16(bb + AT_PB + sV, Vb + (size_t)rv * 1024 + ko + cv);
            CP_COMMIT();
        }
        if (tid < 128) {
            float s = 0.0f;
#pragma unroll
            for (int t = 0; t < 8; t++)
                s += g_psum[((size_t)bh * 8 + t) * Sc + q0 + tid];
            sinv[tid] = 1.0f / s;
        }

        for (int kt = 0; kt < 32; kt++) {
            const int w = 31 - kt;
            if (w >= 2)      cp_wait2();
            else if (w == 1) cp_wait1();
            else             cp_wait0();
            __syncthreads();
            if (kt + 3 <= 31) {
                const int ko = (kt + 3) * 32;
                const uint32_t bb = sb + ((kt + 3) & 3) * AT_BUF;
                cpa16(bb + sP0,        Pe + (size_t)ra0 * 1024 + ko + ca0);
                cpa16(bb + sP1,        Pe + (size_t)ra1 * 1024 + ko + ca1);
                cpa16(bb + AT_PB + sV, Vb + (size_t)rv * 1024 + ko + cv);
                CP_COMMIT();
            }
            const uint32_t pB = sb + (kt & 3) * AT_BUF;
            const uint32_t vB = pB + AT_PB;
            const __half* Ps = (const __half*)(smem + (kt & 3) * AT_BUF);

#pragma unroll
            for (int ks = 0; ks < 2; ks++) {
                const int k0s = ks * 16;
                uint32_t af[2][4], bf[2][4];
#pragma unroll
                for (int mi = 0; mi < 2; mi++)
                    ldsm4(af[mi], pB + (uint32_t)(wm*32 + mi*16 + arow) * AST + (k0s + acol) * 2);
#pragma unroll
                for (int j = 0; j < 2; j++)
                    ldsm4(bf[j], vB + (uint32_t)(wn*32 + j*16 + brow) * AST + (k0s + bcol) * 2);
#pragma unroll
                for (int mi = 0; mi < 2; mi++)
#pragma unroll
                    for (int ni = 0; ni < 4; ni++)
                        mma_f16(acc[mi][ni], af[mi], &bf[ni >> 1][(ni & 1) * 2]);
            }

            // final p write (streaming stores)
            {
                const float s = sinv[r2];
                float* pd = Pout + (size_t)r2 * 1024 + kt * 32 + h16;
                const uint4* psrc = (const uint4*)(Ps + r2 * (AST / 2) + h16);
#pragma unroll
                for (int j = 0; j < 2; j++) {
                    uint4 raw = psrc[j];
                    const __half2* hp = (const __half2*)&raw;
                    float2 f0 = __half22float2(hp[0]);
                    float2 f1 = __half22float2(hp[1]);
                    float2 f2 = __half22float2(hp[2]);
                    float2 f3 = __half22float2(hp[3]);
                    stcs4(pd + j * 8,     make_float4(f0.x * s, f0.y * s, f1.x * s, f1.y * s));
                    stcs4(pd + j * 8 + 4, make_float4(f2.x * s, f2.y * s, f3.x * s, f3.y * s));
                }
            }
        }
        __syncthreads();   // loop reads done before stage overwrites buffers

        // epilogue: O *= inv
        float* stage = (float*)smem;   // [128][68]
#pragma unroll
        for (int mi = 0; mi < 2; mi++) {
            const int row = wm * 32 + mi * 16 + (lane >> 2);
            const float i1 = sinv[row], i2 = sinv[row + 8];
#pragma unroll
            for (int ni = 0; ni < 4; ni++) {
                const int col = wn * 32 + ni * 8 + (lane & 3) * 2;
                *(float2*)&stage[row * ATG + col]       = make_float2(acc[mi][ni][0] * i1, acc[mi][ni][1] * i1);
                *(float2*)&stage[(row + 8) * ATG + col] = make_float2(acc[mi][ni][2] * i2, acc[mi][ni][3] * i2);
            }
        }
        __syncthreads();

        const int b = bh >> 4, h = bh & 15;
#pragma unroll
        for (int i = 0; i < 8; i++) {
            const int e = tid + i * 256;
            const int r = e >> 4, c4 = (e & 15) * 4;
            float4 v = *(const float4*)&stage[r * ATG + c4];
            uint2 hv = make_uint2(packh2(v.x, v.y), packh2(v.z, v.w));
            *(uint2*)(g_att + ((size_t)(b * 1024) + q0 + r) * 1024 + h * 64 + c4) = hv;
        }
        __syncthreads();   // stage reads done before next unit's prologue
    }
}

// ---------------- LayerNorm ----------------
__global__ __launch_bounds__(256) void ln_kernel(const float* __restrict__ gg_,
                                                 const float* __restrict__ bta,
                                                 float* __restrict__ y)
{
    __shared__ float s1[8], s2[8];
    const int row = blockIdx.x, tid = threadIdx.x, lane = tid & 31, w = tid >> 5;
    const float* xr = g_fc + (size_t)row * 1024;

    float4 v = *(const float4*)(xr + tid * 4);
    float s = v.x + v.y + v.z + v.w;
    float q = v.x*v.x + v.y*v.y + v.z*v.z + v.w*v.w;
#pragma unroll
    for (int o = 16; o > 0; o >>= 1) {
        s += __shfl_xor_sync(0xffffffffu, s, o);
        q += __shfl_xor_sync(0xffffffffu, q, o);
    }
    if (lane == 0) { s1[w] = s; s2[w] = q; }
    __syncthreads();
    s = 0.0f; q = 0.0f;
#pragma unroll
    for (int i = 0; i < 8; i++) { s += s1[i]; q += s2[i]; }

    const float mu  = s * (1.0f / 1024.0f);
    const float var = q * (1.0f / 1024.0f) - mu * mu;
    const float rs  = rsqrtf(var + 1e-5f);

    float4 gv = *(const float4*)(gg_ + tid * 4);
    float4 bb = *(const float4*)(bta + tid * 4);
    float4 o;
    o.x = (v.x - mu) * rs * gv.x + bb.x;
    o.y = (v.y - mu) * rs * gv.y + bb.y;
    o.z = (v.z - mu) * rs * gv.z + bb.z;
    o.w = (v.w - mu) * rs * gv.w + bb.w;
    *(float4*)(y + (size_t)row * 1024 + tid * 4) = o;
}

// ---------------------------------------------------------------------------
extern "C" void kernel_launch(void* const* d_in, const int* in_sizes, int n_in,
                              void* d_out, int out_size)
{
    const float* query    = (const float*)d_in[0];
    const float* key      = (const float*)d_in[1];
    const float* value    = (const float*)d_in[2];
    const int*   mask     = (const int*)  d_in[3];
    const float* relation = (const float*)d_in[4];
    const float* Wq       = (const float*)d_in[5];
    const float* Wk       = (const float*)d_in[6];
    const float* Wv       = (const float*)d_in[7];
    const float* fc_w     = (const float*)d_in[8];
    const float* fc_b     = (const float*)d_in[9];
    const float* ln_g     = (const float*)d_in[10];
    const float* ln_b     = (const float*)d_in[11];

    float* y = (float*)d_out;
    float* p = y + (size_t)YSIZE;

    static bool attr_set = false;
    if (!attr_set) {
        cudaFuncSetAttribute(mma_gemm,   cudaFuncAttributeMaxDynamicSharedMemorySize, SM_G);
        cudaFuncSetAttribute(scores_mma, cudaFuncAttributeMaxDynamicSharedMemorySize, SM_S);
        cudaFuncSetAttribute(att_mma,    cudaFuncAttributeMaxDynamicSharedMemorySize, SM_A);
        attr_set = true;
    }

    transpose_w<<<dim3(32, 32, 4), dim3(32, 8)>>>(Wq, Wk, Wv, fc_w);

    // QKV projections: one merged launch
    mma_gemm<<<dim3(8, 32, 3), 256, SM_G>>>(query, key, value, -1, nullptr, nullptr);

    scores_mma<<<dim3(8, 8, 64), 256, SM_S>>>(relation, mask);
    att_mma<<<dim3(4, 64), 256, SM_A>>>(p);

    mma_gemm<<<dim3(8, 32, 1), 256, SM_G>>>(nullptr, nullptr, nullptr, 3, fc_b, query);
    ln_kernel<<<Mc, 256>>>(ln_g, ln_b, y);
}

// round 17
// speedup vs baseline: 1.0113x; 1.0113x over previous
#include <cuda_runtime.h>
#include <cuda_fp16.h>
#include <math.h>
#include <stdint.h>

#define Bc   4
#define Sc   1024
#define Dc   1024
#define Hc   16
#define DKc  64
#define Mc   (Bc*Sc)        // 4096
#define BHc  (Bc*Hc)        // 64
#define YSIZE (Bc*Sc*Dc)

// ---------------- device scratch ----------------
__device__ __half g_Q[Mc*Dc];       // [bh][s][dk] fp16
__device__ __half g_K[Mc*Dc];       // [bh][s][dk] fp16
__device__ __half g_VT[Mc*Dc];      // [bh][dk][s] fp16
__device__ __half g_att[Mc*Dc];     // [m][h*dk]  fp16
__device__ float g_fc[Mc*Dc];       // fc + resid (fp32)
__device__ __half g_WT[4][Dc*Dc];   // WT[n][k] fp16
__device__ float g_psum[BHc*8*Sc];  // [bh][nt][q] partial row sums
__device__ __half g_pexp[(size_t)BHc*Sc*Sc];  // unnormalized exp(x), fp16

// ---------------- helpers ----------------
__device__ __forceinline__ uint32_t smem_u32(const void* p) {
    uint32_t a;
    asm("{ .reg .u64 t; cvta.to.shared.u64 t, %1; cvt.u32.u64 %0, t; }" : "=r"(a) : "l"(p));
    return a;
}
__device__ __forceinline__ uint32_t packh2(float x, float y) {
    __half2 h = __float22half2_rn(make_float2(x, y));
    return *(uint32_t*)&h;
}
__device__ __forceinline__ void ldsm4(uint32_t* r, uint32_t addr) {
    asm volatile("ldmatrix.sync.aligned.m8n8.x4.shared.b16 {%0,%1,%2,%3}, [%4];"
        : "=r"(r[0]), "=r"(r[1]), "=r"(r[2]), "=r"(r[3]) : "r"(addr));
}
__device__ __forceinline__ void mma_f16(float* c, const uint32_t* a, const uint32_t* b) {
    asm volatile("mma.sync.aligned.m16n8k16.row.col.f32.f16.f16.f32 "
        "{%0,%1,%2,%3}, {%4,%5,%6,%7}, {%8,%9}, {%0,%1,%2,%3};"
        : "+f"(c[0]), "+f"(c[1]), "+f"(c[2]), "+f"(c[3])
        : "r"(a[0]), "r"(a[1]), "r"(a[2]), "r"(a[3]), "r"(b[0]), "r"(b[1]));
}
__device__ __forceinline__ void cpa16(uint32_t dst, const void* src) {
    asm volatile("cp.async.cg.shared.global [%0], [%1], 16;" :: "r"(dst), "l"(src));
}
#define CP_COMMIT() asm volatile("cp.async.commit_group;" ::: "memory")
__device__ __forceinline__ void cp_wait(int n) {
    if (n == 0) asm volatile("cp.async.wait_group 0;" ::: "memory");
    else        asm volatile("cp.async.wait_group 1;" ::: "memory");
}

// ---------------- weight transpose: W[k][n] -> WT[n][k] fp16 ----------------
__global__ void transpose_w(const float* __restrict__ W0, const float* __restrict__ W1,
                            const float* __restrict__ W2, const float* __restrict__ W3)
{
    __shared__ float t[32][33];
    const float* W = (blockIdx.z == 0) ? W0 : (blockIdx.z == 1) ? W1 : (blockIdx.z == 2) ? W2 : W3;
    __half* o = g_WT[blockIdx.z];
    const int k0 = blockIdx.y * 32, n0 = blockIdx.x * 32;
    const int tx = threadIdx.x, ty = threadIdx.y;   // 32 x 8
#pragma unroll
    for (int i = 0; i < 32; i += 8)
        t[ty + i][tx] = W[(size_t)(k0 + ty + i) * Dc + n0 + tx];
    __syncthreads();
#pragma unroll
    for (int i = 0; i < 32; i += 8)
        o[(size_t)(n0 + ty + i) * Dc + k0 + tx] = __float2half(t[tx][ty + i]);
}

// ===========================================================================
// fp16 GEMM, 3-stage cp.async pipeline, ONE barrier per k-tile (as R14).
// ===========================================================================
#define GRS 80
#define GTILE 10240
#define GBUF  (2*GTILE)
#define SM_G  (128*132*4)
#define STG 132

__global__ __launch_bounds__(256, 2) void mma_gemm(const float* __restrict__ A0,
                                                   const float* __restrict__ A1,
                                                   const float* __restrict__ A2,
                                                   int modeParam,
                                                   const float* __restrict__ bias,
                                                   const float* __restrict__ resid)
{
    extern __shared__ __align__(16) char smem[];
    const uint32_t sb = smem_u32(smem);
    const int tid  = threadIdx.x;
    const int lane = tid & 31;
    const int wid  = tid >> 5;
    const int wm   = wid >> 2;
    const int wn   = wid & 3;
    const int m0 = blockIdx.y * 128;
    const int n0 = blockIdx.x * 128;

    const int mode = (modeParam >= 0) ? modeParam : (int)blockIdx.z;
    const bool a16 = (mode == 3);
    const float* Af = (mode == 0) ? A0 : (mode == 1) ? A1 : A2;
    const __half* B = g_WT[mode];

    const int fr3 = tid >> 3, fc3 = (tid & 7) * 4;
    const int ra0 = tid >> 2,          ca0 = (tid & 3) * 8;
    const int ra1 = (tid + 256) >> 2,  ca1 = ((tid + 256) & 3) * 8;
    const uint32_t sA0 = ra0 * GRS + ca0 * 2;
    const uint32_t sA1 = ra1 * GRS + ca1 * 2;

    const int arow = lane & 15;
    const int acol = (lane & 16) ? 8 : 0;
    const int brow = ((lane & 16) >> 1) + (lane & 7);
    const int bcol = (lane & 8);

    float acc[4][4][4];
#pragma unroll
    for (int i = 0; i < 4; i++)
#pragma unroll
        for (int j = 0; j < 4; j++)
#pragma unroll
            for (int q = 0; q < 4; q++) acc[i][j][q] = 0.0f;

    float4 pa[4];
    {
        cpa16(sb + GTILE + sA0, B + (size_t)(n0 + ra0) * 1024 + ca0);
        cpa16(sb + GTILE + sA1, B + (size_t)(n0 + ra1) * 1024 + ca1);
        if (a16) {
            cpa16(sb + sA0, g_att + (size_t)(m0 + ra0) * 1024 + ca0);
            cpa16(sb + sA1, g_att + (size_t)(m0 + ra1) * 1024 + ca1);
        }
        CP_COMMIT();
        cpa16(sb + GBUF + GTILE + sA0, B + (size_t)(n0 + ra0) * 1024 + 32 + ca0);
        cpa16(sb + GBUF + GTILE + sA1, B + (size_t)(n0 + ra1) * 1024 + 32 + ca1);
        if (a16) {
            cpa16(sb + GBUF + sA0, g_att + (size_t)(m0 + ra0) * 1024 + 32 + ca0);
            cpa16(sb + GBUF + sA1, g_att + (size_t)(m0 + ra1) * 1024 + 32 + ca1);
        }
        CP_COMMIT();
    }
    if (!a16) {
#pragma unroll
        for (int j = 0; j < 4; j++)
            pa[j] = *(const float4*)(Af + (size_t)(m0 + fr3 + 32 * j) * 1024 + fc3);
        char* As = smem;
#pragma unroll
        for (int j = 0; j < 4; j++) {
            uint2 h = make_uint2(packh2(pa[j].x, pa[j].y), packh2(pa[j].z, pa[j].w));
            *(uint2*)(As + (fr3 + 32 * j) * GRS + fc3 * 2) = h;
        }
#pragma unroll
        for (int j = 0; j < 4; j++)
            pa[j] = *(const float4*)(Af + (size_t)(m0 + fr3 + 32 * j) * 1024 + 32 + fc3);
    }

    for (int kt = 0; kt < 32; kt++) {
        cp_wait(kt == 31 ? 0 : 1);
        __syncthreads();
        if (kt + 2 <= 31) {
            const int ko = (kt + 2) * 32;
            const uint32_t bb = sb + ((kt + 2) % 3) * GBUF;
            cpa16(bb + GTILE + sA0, B + (size_t)(n0 + ra0) * 1024 + ko + ca0);
            cpa16(bb + GTILE + sA1, B + (size_t)(n0 + ra1) * 1024 + ko + ca1);
            if (a16) {
                cpa16(bb + sA0, g_att + (size_t)(m0 + ra0) * 1024 + ko + ca0);
                cpa16(bb + sA1, g_att + (size_t)(m0 + ra1) * 1024 + ko + ca1);
            }
            CP_COMMIT();
        }
        const uint32_t aB = sb + (kt % 3) * GBUF;
        const uint32_t bB = aB + GTILE;
#pragma unroll
        for (int ks = 0; ks < 2; ks++) {
            const int k0s = ks * 16;
            uint32_t af[4][4], bf[2][4];
#pragma unroll
            for (int mi = 0; mi < 4; mi++)
                ldsm4(af[mi], aB + (uint32_t)(wm*64 + mi*16 + arow) * GRS + (k0s + acol) * 2);
#pragma unroll
            for (int j = 0; j < 2; j++)
                ldsm4(bf[j], bB + (uint32_t)(wn*32 + j*16 + brow) * GRS + (k0s + bcol) * 2);
#pragma unroll
            for (int mi = 0; mi < 4; mi++)
#pragma unroll
                for (int ni = 0; ni < 4; ni++)
                    mma_f16(acc[mi][ni], af[mi], &bf[ni >> 1][(ni & 1) * 2]);
        }
        if (!a16) {
            if (kt + 1 <= 31) {
                char* As2 = smem + ((kt + 1) % 3) * GBUF;
#pragma unroll
                for (int j = 0; j < 4; j++) {
                    uint2 h = make_uint2(packh2(pa[j].x, pa[j].y), packh2(pa[j].z, pa[j].w));
                    *(uint2*)(As2 + (fr3 + 32 * j) * GRS + fc3 * 2) = h;
                }
            }
            if (kt + 2 <= 31) {
                const int ko = (kt + 2) * 32;
#pragma unroll
                for (int j = 0; j < 4; j++)
                    pa[j] = *(const float4*)(Af + (size_t)(m0 + fr3 + 32 * j) * 1024 + ko + fc3);
            }
        }
    }
    __syncthreads();

    float* stage = (float*)smem;
#pragma unroll
    for (int mi = 0; mi < 4; mi++)
#pragma unroll
        for (int ni = 0; ni < 4; ni++) {
            const int row = wm * 64 + mi * 16 + (lane >> 2);
            const int col = wn * 32 + ni * 8 + (lane & 3) * 2;
            *(float2*)&stage[row * STG + col]       = make_float2(acc[mi][ni][0], acc[mi][ni][1]);
            *(float2*)&stage[(row + 8) * STG + col] = make_float2(acc[mi][ni][2], acc[mi][ni][3]);
        }
    __syncthreads();

    if (mode <= 1) {
        __half* out = (mode == 0) ? g_Q : g_K;
#pragma unroll
        for (int i = 0; i < 16; i++) {
            const int e = tid + i * 256;
            const int r = e >> 5, c4 = (e & 31) * 4;
            float4 v = *(const float4*)&stage[r * STG + c4];
            const int m = m0 + r, b = m >> 10, s = m & 1023;
            const int n = n0 + c4, h = n >> 6, dk = n & 63;
            uint2 hv = make_uint2(packh2(v.x, v.y), packh2(v.z, v.w));
            *(uint2*)(out + (((size_t)(b * 16 + h) * 1024 + s) * 64 + dk)) = hv;
        }
    } else if (mode == 2) {
        const int r = tid & 127, half_ = tid >> 7;
        const int b = m0 >> 10, s0r = m0 & 1023;
#pragma unroll 8
        for (int j = 0; j < 64; j++) {
            const int c = half_ * 64 + j;
            const float v = stage[r * STG + c];
            const int n = n0 + c, hh = n >> 6, dk = n & 63;
            g_VT[((size_t)(b * 16 + hh) * 64 + dk) * 1024 + s0r + r] = __float2half(v);
        }
    } else {
#pragma unroll
        for (int i = 0; i < 16; i++) {
            const int e = tid + i * 256;
            const int r = e >> 5, c4 = (e & 31) * 4;
            float4 v = *(const float4*)&stage[r * STG + c4];
            const int m = m0 + r, n = n0 + c4;
            float4 bi = *(const float4*)(bias + n);
            float4 rs = *(const float4*)(resid + (size_t)m * 1024 + n);
            v.x += bi.x + rs.x; v.y += bi.y + rs.y;
            v.z += bi.z + rs.z; v.w += bi.w + rs.w;
            *(float4*)(g_fc + (size_t)m * 1024 + n) = v;
        }
    }
}

// ===========================================================================
// scores (fp16 mma, no-max softmax) — unchanged from R12.
// ===========================================================================
#define SRS 144
#define SM_S (128*132*4)

__global__ __launch_bounds__(256, 2) void scores_mma(const float* __restrict__ rel,
                                                     const int*   __restrict__ mask)
{
    extern __shared__ __align__(16) char smem[];
    const uint32_t sb = smem_u32(smem);
    const uint32_t qB = sb, kB = sb + 128 * SRS;

    const int tid = threadIdx.x, lane = tid & 31, wid = tid >> 5;
    const int wm = wid >> 2, wn = wid & 3;
    const int bh = blockIdx.z, q0 = blockIdx.y * 128, n0 = blockIdx.x * 128;
    const size_t base = (size_t)bh * Sc * DKc;

    const int arow = lane & 15;
    const int acol = (lane & 16) ? 8 : 0;
    const int brow = ((lane & 16) >> 1) + (lane & 7);
    const int bcol = (lane & 8);

    {
#pragma unroll
        for (int i = 0; i < 4; i++) {
            const int e = tid + i * 256;
            const int r = e >> 3, c16 = (e & 7) * 8;
            cpa16(qB + (uint32_t)r * SRS + c16 * 2, g_Q + base + (size_t)(q0 + r) * 64 + c16);
            cpa16(kB + (uint32_t)r * SRS + c16 * 2, g_K + base + (size_t)(n0 + r) * 64 + c16);
        }
        CP_COMMIT();
        cp_wait(0);
    }
    __syncthreads();

    float acc[4][4][4];
#pragma unroll
    for (int i = 0; i < 4; i++)
#pragma unroll
        for (int j = 0; j < 4; j++)
#pragma unroll
            for (int q = 0; q < 4; q++) acc[i][j][q] = 0.0f;

#pragma unroll
    for (int ks = 0; ks < 4; ks++) {
        const int k0s = ks * 16;
        uint32_t af[4][4], bf[2][4];
#pragma unroll
        for (int mi = 0; mi < 4; mi++)
            ldsm4(af[mi], qB + (uint32_t)(wm*64 + mi*16 + arow) * SRS + (k0s + acol) * 2);
#pragma unroll
        for (int j = 0; j < 2; j++)
            ldsm4(bf[j], kB + (uint32_t)(wn*32 + j*16 + brow) * SRS + (k0s + bcol) * 2);
#pragma unroll
        for (int mi = 0; mi < 4; mi++)
#pragma unroll
            for (int ni = 0; ni < 4; ni++)
                mma_f16(acc[mi][ni], af[mi], &bf[ni >> 1][(ni & 1) * 2]);
    }
    __syncthreads();

    float* stage = (float*)smem;
#pragma unroll
    for (int mi = 0; mi < 4; mi++)
#pragma unroll
        for (int ni = 0; ni < 4; ni++) {
            const int row = wm * 64 + mi * 16 + (lane >> 2);
            const int col = wn * 32 + ni * 8 + (lane & 3) * 2;
            *(float2*)&stage[row * STG + col]       = make_float2(acc[mi][ni][0], acc[mi][ni][1]);
            *(float2*)&stage[(row + 8) * STG + col] = make_float2(acc[mi][ni][2], acc[mi][ni][3]);
        }
    __syncthreads();

    const int b = bh >> 4;
#pragma unroll
    for (int i = 0; i < 16; i++) {
        const int r = i * 8 + wid;
        const int q = q0 + r;
        const int n = n0 + lane * 4;
        float4 v = *(const float4*)&stage[r * STG + lane * 4];
        const size_t ridx = ((size_t)b * Sc + q) * Sc + n;
        float4 r4 = *(const float4*)(rel + ridx);
        int4   m4 = *(const int4*)(mask + ridx);
        float4 e;
        e.x = m4.x ? 0.0f : __expf(fmaf(v.x, 0.125f, r4.x));
        e.y = m4.y ? 0.0f : __expf(fmaf(v.y, 0.125f, r4.y));
        e.z = m4.z ? 0.0f : __expf(fmaf(v.z, 0.125f, r4.z));
        e.w = m4.w ? 0.0f : __expf(fmaf(v.w, 0.125f, r4.w));
        float s = e.x + e.y + e.z + e.w;
#pragma unroll
        for (int o = 16; o > 0; o >>= 1) s += __shfl_xor_sync(0xffffffffu, s, o);
        uint2 hw = make_uint2(packh2(e.x, e.y), packh2(e.z, e.w));
        *(uint2*)(g_pexp + ((size_t)bh * Sc + q) * Sc + n) = hw;
        if (lane == 0)
            g_psum[((size_t)bh * 8 + blockIdx.x) * Sc + q] = s;
    }
}

// ===========================================================================
// att (fp16 mma): grid (8,64), k-tile 32, 3-stage pipeline, 1 barrier/tile,
// OCCUPANCY 3 (reg cap 85 — acc is only 32 regs). p-write via uint4 smem reads.
// ===========================================================================
#define AST 80
#define AT_PB (128*AST)             // 10240
#define AT_VB (64*AST)              // 5120
#define AT_BUF (AT_PB+AT_VB)        // 15360; 3 stages = 46080
#define AT_SINV 46080
#define SM_A (AT_SINV + 512)        // 46592; 3 CTAs = 139776 <= 228KB
#define ATG 68

__global__ __launch_bounds__(256, 3) void att_mma(float* __restrict__ p)
{
    extern __shared__ __align__(16) char smem[];
    const uint32_t sb = smem_u32(smem);
    float* sinv = (float*)(smem + AT_SINV);   // [128]

    const int tid = threadIdx.x, lane = tid & 31, wid = tid >> 5;
    const int wm = wid >> 1, wn = wid & 1;
    const int q0 = blockIdx.x * 128, bh = blockIdx.y;
    const __half* Pe = g_pexp + ((size_t)bh * 1024 + q0) * 1024;
    float* Pout = p + ((size_t)bh * 1024 + q0) * 1024;
    const __half* Vb = g_VT + (size_t)bh * 64 * 1024;

    const int ra0 = tid >> 2,          ca0 = (tid & 3) * 8;
    const int ra1 = (tid + 256) >> 2,  ca1 = ((tid + 256) & 3) * 8;
    const uint32_t sP0 = ra0 * AST + ca0 * 2;
    const uint32_t sP1 = ra1 * AST + ca1 * 2;
    const int rv = tid >> 2,           cv = (tid & 3) * 8;
    const uint32_t sV = rv * AST + cv * 2;
    const int r2 = tid >> 1, h16 = (tid & 1) * 16;

    const int arow = lane & 15;
    const int acol = (lane & 16) ? 8 : 0;
    const int brow = ((lane & 16) >> 1) + (lane & 7);
    const int bcol = (lane & 8);

    float acc[2][4][4];
#pragma unroll
    for (int i = 0; i < 2; i++)
#pragma unroll
        for (int j = 0; j < 4; j++)
#pragma unroll
            for (int q = 0; q < 4; q++) acc[i][j][q] = 0.0f;

    // prologue: tiles 0 and 1; sinv
    {
        cpa16(sb + sP0,        Pe + (size_t)ra0 * 1024 + ca0);
        cpa16(sb + sP1,        Pe + (size_t)ra1 * 1024 + ca1);
        cpa16(sb + AT_PB + sV, Vb + (size_t)rv * 1024 + cv);
        CP_COMMIT();
        cpa16(sb + AT_BUF + sP0,        Pe + (size_t)ra0 * 1024 + 32 + ca0);
        cpa16(sb + AT_BUF + sP1,        Pe + (size_t)ra1 * 1024 + 32 + ca1);
        cpa16(sb + AT_BUF + AT_PB + sV, Vb + (size_t)rv * 1024 + 32 + cv);
        CP_COMMIT();
    }
    if (tid < 128) {
        float s = 0.0f;
#pragma unroll
        for (int t = 0; t < 8; t++)
            s += g_psum[((size_t)bh * 8 + t) * Sc + q0 + tid];
        sinv[tid] = 1.0f / s;
    }

    for (int kt = 0; kt < 32; kt++) {
        cp_wait(kt == 31 ? 0 : 1);
        __syncthreads();
        if (kt + 2 <= 31) {
            const int ko = (kt + 2) * 32;
            const uint32_t bb = sb + ((kt + 2) % 3) * AT_BUF;
            cpa16(bb + sP0,        Pe + (size_t)ra0 * 1024 + ko + ca0);
            cpa16(bb + sP1,        Pe + (size_t)ra1 * 1024 + ko + ca1);
            cpa16(bb + AT_PB + sV, Vb + (size_t)rv * 1024 + ko + cv);
            CP_COMMIT();
        }
        const uint32_t pB = sb + (kt % 3) * AT_BUF;
        const uint32_t vB = pB + AT_PB;
        const __half* Ps = (const __half*)(smem + (kt % 3) * AT_BUF);

#pragma unroll
        for (int ks = 0; ks < 2; ks++) {
            const int k0s = ks * 16;
            uint32_t af[2][4], bf[2][4];
#pragma unroll
            for (int mi = 0; mi < 2; mi++)
                ldsm4(af[mi], pB + (uint32_t)(wm*32 + mi*16 + arow) * AST + (k0s + acol) * 2);
#pragma unroll
            for (int j = 0; j < 2; j++)
                ldsm4(bf[j], vB + (uint32_t)(wn*32 + j*16 + brow) * AST + (k0s + bcol) * 2);
#pragma unroll
            for (int mi = 0; mi < 2; mi++)
#pragma unroll
                for (int ni = 0; ni < 4; ni++)
                    mma_f16(acc[mi][ni], af[mi], &bf[ni >> 1][(ni & 1) * 2]);
        }

        // final p write: pexp (smem, uint4 loads) * inv -> fp32 global
        {
            const float s = sinv[r2];
            float* pd = Pout + (size_t)r2 * 1024 + kt * 32 + h16;
            const uint4* psrc = (const uint4*)(Ps + r2 * (AST / 2) + h16);
#pragma unroll
            for (int j = 0; j < 2; j++) {
                uint4 raw = psrc[j];
                const __half2* hp = (const __half2*)&raw;
                float2 f0 = __half22float2(hp[0]);
                float2 f1 = __half22float2(hp[1]);
                float2 f2 = __half22float2(hp[2]);
                float2 f3 = __half22float2(hp[3]);
                *(float4*)(pd + j * 8)     = make_float4(f0.x * s, f0.y * s, f1.x * s, f1.y * s);
                *(float4*)(pd + j * 8 + 4) = make_float4(f2.x * s, f2.y * s, f3.x * s, f3.y * s);
            }
        }
    }
    __syncthreads();

    // epilogue: O *= inv
    float* stage = (float*)smem;   // [128][68]
#pragma unroll
    for (int mi = 0; mi < 2; mi++) {
        const int row = wm * 32 + mi * 16 + (lane >> 2);
        const float i1 = sinv[row], i2 = sinv[row + 8];
#pragma unroll
        for (int ni = 0; ni < 4; ni++) {
            const int col = wn * 32 + ni * 8 + (lane & 3) * 2;
            *(float2*)&stage[row * ATG + col]       = make_float2(acc[mi][ni][0] * i1, acc[mi][ni][1] * i1);
            *(float2*)&stage[(row + 8) * ATG + col] = make_float2(acc[mi][ni][2] * i2, acc[mi][ni][3] * i2);
        }
    }
    __syncthreads();

    const int b = bh >> 4, h = bh & 15;
#pragma unroll
    for (int i = 0; i < 8; i++) {
        const int e = tid + i * 256;
        const int r = e >> 4, c4 = (e & 15) * 4;
        float4 v = *(const float4*)&stage[r * ATG + c4];
        uint2 hv = make_uint2(packh2(v.x, v.y), packh2(v.z, v.w));
        *(uint2*)(g_att + ((size_t)(b * 1024) + q0 + r) * 1024 + h * 64 + c4) = hv;
    }
}

// ---------------- LayerNorm ----------------
__global__ __launch_bounds__(256) void ln_kernel(const float* __restrict__ gg_,
                                                 const float* __restrict__ bta,
                                                 float* __restrict__ y)
{
    __shared__ float s1[8], s2[8];
    const int row = blockIdx.x, tid = threadIdx.x, lane = tid & 31, w = tid >> 5;
    const float* xr = g_fc + (size_t)row * 1024;

    float4 v = *(const float4*)(xr + tid * 4);
    float s = v.x + v.y + v.z + v.w;
    float q = v.x*v.x + v.y*v.y + v.z*v.z + v.w*v.w;
#pragma unroll
    for (int o = 16; o > 0; o >>= 1) {
        s += __shfl_xor_sync(0xffffffffu, s, o);
        q += __shfl_xor_sync(0xffffffffu, q, o);
    }
    if (lane == 0) { s1[w] = s; s2[w] = q; }
    __syncthreads();
    s = 0.0f; q = 0.0f;
#pragma unroll
    for (int i = 0; i < 8; i++) { s += s1[i]; q += s2[i]; }

    const float mu  = s * (1.0f / 1024.0f);
    const float var = q * (1.0f / 1024.0f) - mu * mu;
    const float rs  = rsqrtf(var + 1e-5f);

    float4 gv = *(const float4*)(gg_ + tid * 4);
    float4 bb = *(const float4*)(bta + tid * 4);
    float4 o;
    o.x = (v.x - mu) * rs * gv.x + bb.x;
    o.y = (v.y - mu) * rs * gv.y + bb.y;
    o.z = (v.z - mu) * rs * gv.z + bb.z;
    o.w = (v.w - mu) * rs * gv.w + bb.w;
    *(float4*)(y + (size_t)row * 1024 + tid * 4) = o;
}

// ---------------------------------------------------------------------------
extern "C" void kernel_launch(void* const* d_in, const int* in_sizes, int n_in,
                              void* d_out, int out_size)
{
    const float* query    = (const float*)d_in[0];
    const float* key      = (const float*)d_in[1];
    const float* value    = (const float*)d_in[2];
    const int*   mask     = (const int*)  d_in[3];
    const float* relation = (const float*)d_in[4];
    const float* Wq       = (const float*)d_in[5];
    const float* Wk       = (const float*)d_in[6];
    const float* Wv       = (const float*)d_in[7];
    const float* fc_w     = (const float*)d_in[8];
    const float* fc_b     = (const float*)d_in[9];
    const float* ln_g     = (const float*)d_in[10];
    const float* ln_b     = (const float*)d_in[11];

    float* y = (float*)d_out;
    float* p = y + (size_t)YSIZE;

    static bool attr_set = false;
    if (!attr_set) {
        cudaFuncSetAttribute(mma_gemm,   cudaFuncAttributeMaxDynamicSharedMemorySize, SM_G);
        cudaFuncSetAttribute(scores_mma, cudaFuncAttributeMaxDynamicSharedMemorySize, SM_S);
        cudaFuncSetAttribute(att_mma,    cudaFuncAttributeMaxDynamicSharedMemorySize, SM_A);
        attr_set = true;
    }

    transpose_w<<<dim3(32, 32, 4), dim3(32, 8)>>>(Wq, Wk, Wv, fc_w);

    // QKV projections: one merged launch
    mma_gemm<<<dim3(8, 32, 3), 256, SM_G>>>(query, key, value, -1, nullptr, nullptr);

    scores_mma<<<dim3(8, 8, 64), 256, SM_S>>>(relation, mask);
    att_mma<<<dim3(8, 64), 256, SM_A>>>(p);

    mma_gemm<<<dim3(8, 32, 1), 256, SM_G>>>(nullptr, nullptr, nullptr, 3, fc_b, query);
    ln_kernel<<<Mc, 256>>>(ln_g, ln_b, y);
}